// round 8
// baseline (speedup 1.0000x reference)
#include <cuda_runtime.h>
#include <cuda_bf16.h>
#include <math.h>
#include <stdint.h>

// ---------------- problem constants ----------------
#define N_NODES   131072
#define G_GRAPHS  1024
#define NPG0      128
#define H_DIM     128
#define E_EDGES   2097152
#define EPG       2048
#define L_LAYERS  3
#define C_CLASSES 10
#define BN_EPS    1e-5f
#define INV_SQRT2 0.70710678118654752440f
#define N_SLOTS   10

#define PLANE_AB  ((size_t)N_NODES * H_DIM)        // plane stride (elems) bufA/bufB
#define PLANE_X   ((size_t)(N_NODES / 2) * H_DIM)  // plane stride bufX

// ---------------- scratch (reinterpreted as bf16 plane pairs) ----------------
__device__ float g_bufA[(size_t)N_NODES * H_DIM];   // hi|lo planes (bf16)
__device__ float g_bufB[(size_t)N_NODES * H_DIM];
__device__ float g_X[(size_t)(N_NODES / 2) * H_DIM];
__device__ float g_embraw[L_LAYERS * G_GRAPHS * H_DIM];
__device__ float g_statsAll[N_SLOTS * 256];
__device__ __nv_bfloat16 g_wimg[7 * 2 * 16384];     // [7 weights][hi|lo][K=128][N=128]

// ---------------- helpers ----------------
__device__ __forceinline__ uint32_t smem_u32(const void* p) {
    uint32_t a;
    asm("{ .reg .u64 t; cvta.to.shared.u64 t, %1; cvt.u32.u64 %0, t; }" : "=r"(a) : "l"(p));
    return a;
}
__device__ __forceinline__ uint32_t pack2(__nv_bfloat16 a, __nv_bfloat16 b) {
    __nv_bfloat162 t; t.x = a; t.y = b; return *(uint32_t*)&t;
}
__device__ __forceinline__ float bflo(uint32_t w) {
    __nv_bfloat162 t = *(__nv_bfloat162*)&w; return __bfloat162float(t.x);
}
__device__ __forceinline__ float bfhi(uint32_t w) {
    __nv_bfloat162 t = *(__nv_bfloat162*)&w; return __bfloat162float(t.y);
}
#define LDSM_X4(r, a) \
    asm volatile("ldmatrix.sync.aligned.m8n8.x4.shared.b16 {%0,%1,%2,%3}, [%4];" \
        : "=r"((r)[0]), "=r"((r)[1]), "=r"((r)[2]), "=r"((r)[3]) : "r"(a))
#define LDSM_X4T(r, a) \
    asm volatile("ldmatrix.sync.aligned.m8n8.x4.trans.shared.b16 {%0,%1,%2,%3}, [%4];" \
        : "=r"((r)[0]), "=r"((r)[1]), "=r"((r)[2]), "=r"((r)[3]) : "r"(a))
#define MMA_BF16(d, a, b0, b1) \
    asm volatile("mma.sync.aligned.m16n8k16.row.col.f32.bf16.bf16.f32 " \
        "{%0,%1,%2,%3}, {%4,%5,%6,%7}, {%8,%9}, {%0,%1,%2,%3};" \
        : "+f"((d)[0]), "+f"((d)[1]), "+f"((d)[2]), "+f"((d)[3]) \
        : "r"((a)[0]), "r"((a)[1]), "r"((a)[2]), "r"((a)[3]), "r"(b0), "r"(b1))

#define SK_BYTES  272   // full-K bf16 row stride (136 elems)
#define AH_BYTES  144   // half-K bf16 row stride (72 elems)

// ---- shared smem layout (both big kernels) ----
#define SB_HI     0
#define SB_LO     34816
#define SA_HI     69632
#define SA_LO     88064
#define SO_BIAS   106496
#define SO_SCALE  107008
#define SO_SHIFT  107520
#define BIG_SMEM  108032

// ---------------- weight bf16 split + stats zero ----------------
__global__ void transw_kernel(const float* __restrict__ w0, const float* __restrict__ w1,
                              const float* __restrict__ w2, __nv_bfloat16* __restrict__ img,
                              float* __restrict__ statsAll) {
    int b = blockIdx.x;
    if (b == 7) {
        for (int i = threadIdx.x; i < N_SLOTS * 256; i += blockDim.x) statsAll[i] = 0.f;
        return;
    }
    const float* W = (b == 0) ? w0 : ((b <= 3) ? w1 + (size_t)(b - 1) * 16384
                                               : w2 + (size_t)(b - 4) * 16384);
    __nv_bfloat16* hi = img + (size_t)b * 32768;
    __nv_bfloat16* lo = hi + 16384;
    for (int i = threadIdx.x; i < 16384; i += blockDim.x) {
        float v = W[i];
        __nv_bfloat16 h = __float2bfloat16(v);
        hi[i] = h;
        lo[i] = __float2bfloat16(v - __bfloat162float(h));
    }
}

// ---------------- A-half loaders ----------------
// (a) fp32 source (stage 0 only)
__device__ __forceinline__ void load_a_half_f32(
    const char* smem, const float4* A4, int kh, int tid) {
    #pragma unroll
    for (int it = 0; it < 4; it++) {
        int i = tid + it * 256;
        int row = i >> 3, g = i & 7;
        float4 u = A4[row * 32 + kh * 16 + g * 2];
        float4 v = A4[row * 32 + kh * 16 + g * 2 + 1];
        float xv[8] = {u.x, u.y, u.z, u.w, v.x, v.y, v.z, v.w};
        uint32_t hp[4], lp[4];
        #pragma unroll
        for (int j = 0; j < 4; j++) {
            __nv_bfloat16 h0 = __float2bfloat16(xv[2 * j]);
            __nv_bfloat16 h1 = __float2bfloat16(xv[2 * j + 1]);
            hp[j] = pack2(h0, h1);
            lp[j] = pack2(__float2bfloat16(xv[2 * j]     - __bfloat162float(h0)),
                          __float2bfloat16(xv[2 * j + 1] - __bfloat162float(h1)));
        }
        uint32_t off = (uint32_t)row * AH_BYTES + (uint32_t)g * 16;
        *(uint4*)(smem + SA_HI + off) = make_uint4(hp[0], hp[1], hp[2], hp[3]);
        *(uint4*)(smem + SA_LO + off) = make_uint4(lp[0], lp[1], lp[2], lp[3]);
    }
}
// (b) plane source, no op: pure copy
__device__ __forceinline__ void load_a_half_copy(
    const char* smem, const uint4* Hi4, const uint4* Lo4, int kh, int tid) {
    #pragma unroll
    for (int it = 0; it < 4; it++) {
        int i = tid + it * 256;
        int row = i >> 3, g = i & 7;
        uint32_t off = (uint32_t)row * AH_BYTES + (uint32_t)g * 16;
        int srci = row * 16 + kh * 8 + g;
        *(uint4*)(smem + SA_HI + off) = Hi4[srci];
        *(uint4*)(smem + SA_LO + off) = Lo4[srci];
    }
}
// (c) plane source + BN+relu (recombine, apply, re-split)
__device__ __forceinline__ void load_a_half_bn(
    const char* smem, const uint4* Hi4, const uint4* Lo4, int kh, int tid,
    const float* sscale, const float* sshift) {
    #pragma unroll
    for (int it = 0; it < 4; it++) {
        int i = tid + it * 256;
        int row = i >> 3, g = i & 7;
        int srci = row * 16 + kh * 8 + g;
        uint4 h = Hi4[srci], l = Lo4[srci];
        uint32_t hw[4] = {h.x, h.y, h.z, h.w}, lw[4] = {l.x, l.y, l.z, l.w};
        int c0 = kh * 64 + g * 8;
        uint32_t hp[4], lp[4];
        #pragma unroll
        for (int j = 0; j < 4; j++) {
            float v0 = bflo(hw[j]) + bflo(lw[j]);
            float v1 = bfhi(hw[j]) + bfhi(lw[j]);
            v0 = fmaxf(fmaf(v0, sscale[c0 + 2 * j],     sshift[c0 + 2 * j]),     0.f);
            v1 = fmaxf(fmaf(v1, sscale[c0 + 2 * j + 1], sshift[c0 + 2 * j + 1]), 0.f);
            __nv_bfloat16 h0 = __float2bfloat16(v0);
            __nv_bfloat16 h1 = __float2bfloat16(v1);
            hp[j] = pack2(h0, h1);
            lp[j] = pack2(__float2bfloat16(v0 - __bfloat162float(h0)),
                          __float2bfloat16(v1 - __bfloat162float(h1)));
        }
        uint32_t off = (uint32_t)row * AH_BYTES + (uint32_t)g * 16;
        *(uint4*)(smem + SA_HI + off) = make_uint4(hp[0], hp[1], hp[2], hp[3]);
        *(uint4*)(smem + SA_LO + off) = make_uint4(lp[0], lp[1], lp[2], lp[3]);
    }
}

// 3-term MMA over one K half
__device__ __forceinline__ void mma_half(
    float acc[2][8][4], uint32_t sb, int kh, int wm, int wn, int lane) {
    const uint32_t aA = sb + SA_HI + (uint32_t)(wm * 32 + (lane & 15)) * AH_BYTES
                      + (uint32_t)(lane >> 4) * 16;
    const uint32_t aB = sb + SB_HI + (uint32_t)(lane & 15) * SK_BYTES
                      + (uint32_t)(wn * 128) + (uint32_t)(lane >> 4) * 16;
    #pragma unroll
    for (int ks = 0; ks < 4; ks++) {
        int kidx = kh * 4 + ks;
        uint32_t ah[2][4], al[2][4], bh[4][4], bl[4][4];
        #pragma unroll
        for (int mt = 0; mt < 2; mt++) {
            uint32_t ad = aA + (uint32_t)mt * (16 * AH_BYTES) + (uint32_t)ks * 32;
            LDSM_X4(ah[mt], ad);
            LDSM_X4(al[mt], ad + (SA_LO - SA_HI));
        }
        #pragma unroll
        for (int nt2 = 0; nt2 < 4; nt2++) {
            uint32_t bd = aB + (uint32_t)kidx * (16 * SK_BYTES) + (uint32_t)nt2 * 32;
            LDSM_X4T(bh[nt2], bd);
            LDSM_X4T(bl[nt2], bd + (SB_LO - SB_HI));
        }
        #pragma unroll
        for (int mt = 0; mt < 2; mt++)
            #pragma unroll
            for (int nt = 0; nt < 8; nt++) {
                uint32_t b0h = bh[nt >> 1][(nt & 1) * 2], b1h = bh[nt >> 1][(nt & 1) * 2 + 1];
                uint32_t b0l = bl[nt >> 1][(nt & 1) * 2], b1l = bl[nt >> 1][(nt & 1) * 2 + 1];
                MMA_BF16(acc[mt][nt], ah[mt], b0h, b1h);
                MMA_BF16(acc[mt][nt], ah[mt], b0l, b1l);
                MMA_BF16(acc[mt][nt], al[mt], b0h, b1h);
            }
    }
}

// epilogue: + bias, stats on fp32 y, store bf16 hi/lo planes
__device__ __forceinline__ void epilogue_planes(
    float acc[2][8][4], const float* sbias,
    __nv_bfloat16* Phi, __nv_bfloat16* Plo, float* statsOut,
    int wm, int wn, int lane) {
    float s[8][2], q[8][2];
    #pragma unroll
    for (int nt = 0; nt < 8; nt++) { s[nt][0] = s[nt][1] = q[nt][0] = q[nt][1] = 0.f; }
    const int cbase = wn * 64 + (lane & 3) * 2;
    const int rbase = wm * 32 + (lane >> 2);
    #pragma unroll
    for (int mt = 0; mt < 2; mt++) {
        int r0 = rbase + mt * 16, r1 = r0 + 8;
        #pragma unroll
        for (int nt = 0; nt < 8; nt++) {
            int c = cbase + nt * 8;
            float b0 = sbias[c], b1 = sbias[c + 1];
            float y0 = acc[mt][nt][0] + b0, y1 = acc[mt][nt][1] + b1;
            float y2 = acc[mt][nt][2] + b0, y3 = acc[mt][nt][3] + b1;
            s[nt][0] += y0 + y2;           s[nt][1] += y1 + y3;
            q[nt][0] += y0 * y0 + y2 * y2; q[nt][1] += y1 * y1 + y3 * y3;
            __nv_bfloat16 h0 = __float2bfloat16(y0), h1 = __float2bfloat16(y1);
            __nv_bfloat16 h2 = __float2bfloat16(y2), h3 = __float2bfloat16(y3);
            *(uint32_t*)(Phi + r0 * 128 + c) = pack2(h0, h1);
            *(uint32_t*)(Phi + r1 * 128 + c) = pack2(h2, h3);
            *(uint32_t*)(Plo + r0 * 128 + c) =
                pack2(__float2bfloat16(y0 - __bfloat162float(h0)),
                      __float2bfloat16(y1 - __bfloat162float(h1)));
            *(uint32_t*)(Plo + r1 * 128 + c) =
                pack2(__float2bfloat16(y2 - __bfloat162float(h2)),
                      __float2bfloat16(y3 - __bfloat162float(h3)));
        }
    }
    #pragma unroll
    for (int off = 16; off >= 4; off >>= 1)
        #pragma unroll
        for (int nt = 0; nt < 8; nt++) {
            s[nt][0] += __shfl_down_sync(0xFFFFFFFFu, s[nt][0], off);
            s[nt][1] += __shfl_down_sync(0xFFFFFFFFu, s[nt][1], off);
            q[nt][0] += __shfl_down_sync(0xFFFFFFFFu, q[nt][0], off);
            q[nt][1] += __shfl_down_sync(0xFFFFFFFFu, q[nt][1], off);
        }
    if (lane < 4) {
        #pragma unroll
        for (int nt = 0; nt < 8; nt++) {
            int c = cbase + nt * 8;
            atomicAdd(&statsOut[c],           s[nt][0]);
            atomicAdd(&statsOut[c + 1],       s[nt][1]);
            atomicAdd(&statsOut[128 + c],     q[nt][0]);
            atomicAdd(&statsOut[128 + c + 1], q[nt][1]);
        }
    }
}

// BN coef setup into smem (threads 0..127), then sync
__device__ __forceinline__ void setup_coefs(
    char* smem, const float* bias, const float* bnG, const float* bnB,
    const float* statsIn, float nIn, int mode, int tid) {
    float* sbias  = (float*)(smem + SO_BIAS);
    float* sscale = (float*)(smem + SO_SCALE);
    float* sshift = (float*)(smem + SO_SHIFT);
    if (tid < 128) {
        sbias[tid] = bias[tid];
        if (mode) {
            float s = statsIn[tid], q = statsIn[128 + tid];
            float m = s / nIn, v = q / nIn - m * m;
            float sc = bnG[tid] * rsqrtf(v + BN_EPS);
            sscale[tid] = sc;
            sshift[tid] = fmaf(-m, sc, bnB[tid]);
        }
    }
    __syncthreads();
}

// copy full B planes (weights) into smem
__device__ __forceinline__ void load_b_planes(char* smem, const __nv_bfloat16* Wimg, int tid) {
    const uint4* bh = (const uint4*)Wimg;
    #pragma unroll
    for (int it = 0; it < 8; it++) {
        int i = tid + it * 256;
        int k = i >> 4, g = i & 15;
        uint32_t off = (uint32_t)k * SK_BYTES + (uint32_t)g * 16;
        *(uint4*)(smem + SB_HI + off) = bh[i];
        *(uint4*)(smem + SB_LO + off) = bh[2048 + i];
    }
}

// ---------------- tc_gemm: planes/fp32 in -> planes out ----------------
// afmt: 0 = fp32 A, 1 = plane A. mode: 1 = BN+relu on A.
__global__ __launch_bounds__(256, 2) void tc_gemm(
    const float* __restrict__ Af,
    const __nv_bfloat16* __restrict__ Ahi, const __nv_bfloat16* __restrict__ Alo,
    const __nv_bfloat16* __restrict__ Wimg, const float* __restrict__ bias,
    const float* __restrict__ bnG, const float* __restrict__ bnB,
    const float* __restrict__ statsIn, float nIn, int afmt, int mode,
    __nv_bfloat16* __restrict__ Ohi, __nv_bfloat16* __restrict__ Olo,
    float* __restrict__ statsOut) {
    extern __shared__ char smem[];
    const uint32_t sb = smem_u32(smem);
    const int tid = threadIdx.x, wid = tid >> 5, lane = tid & 31;
    const int wm = wid >> 1, wn = wid & 1;

    setup_coefs(smem, bias, bnG, bnB, statsIn, nIn, mode, tid);
    load_b_planes(smem, Wimg, tid);

    const float4* A4 = (const float4*)(Af + (size_t)blockIdx.x * 16384);
    const uint4* Hi4 = (const uint4*)(Ahi + (size_t)blockIdx.x * 16384);
    const uint4* Lo4 = (const uint4*)(Alo + (size_t)blockIdx.x * 16384);
    float* sscale = (float*)(smem + SO_SCALE);
    float* sshift = (float*)(smem + SO_SHIFT);

    float acc[2][8][4];
    #pragma unroll
    for (int mt = 0; mt < 2; mt++)
        #pragma unroll
        for (int nt = 0; nt < 8; nt++)
            #pragma unroll
            for (int j = 0; j < 4; j++) acc[mt][nt][j] = 0.f;

    #pragma unroll
    for (int kh = 0; kh < 2; kh++) {
        if (afmt == 0)      load_a_half_f32(smem, A4, kh, tid);
        else if (mode == 0) load_a_half_copy(smem, Hi4, Lo4, kh, tid);
        else                load_a_half_bn(smem, Hi4, Lo4, kh, tid, sscale, sshift);
        __syncthreads();
        mma_half(acc, sb, kh, wm, wn, lane);
        __syncthreads();
    }

    epilogue_planes(acc, (float*)(smem + SO_BIAS),
                    Ohi + (size_t)blockIdx.x * 16384, Olo + (size_t)blockIdx.x * 16384,
                    statsOut, wm, wn, lane);
}

// ---------------- fused layer: H = (I+A)(op(x)@W1) + b1 -> planes --------------
__global__ __launch_bounds__(256, 2) void fused_layer(
    const __nv_bfloat16* __restrict__ Ahi, const __nv_bfloat16* __restrict__ Alo,
    const __nv_bfloat16* __restrict__ W1img,
    const int* __restrict__ src, const int* __restrict__ dst,
    const float* __restrict__ bias,
    const float* __restrict__ bnG, const float* __restrict__ bnB,
    const float* __restrict__ statsIn, float nIn, int mode,
    __nv_bfloat16* __restrict__ Ohi, __nv_bfloat16* __restrict__ Olo,
    float* __restrict__ statsOut, int layer) {
    extern __shared__ char smem[];
    const uint32_t sb = smem_u32(smem);
    const int tid = threadIdx.x, wid = tid >> 5, lane = tid & 31;
    const int wm = wid >> 1, wn = wid & 1;

    setup_coefs(smem, bias, bnG, bnB, statsIn, nIn, mode, tid);
    load_b_planes(smem, W1img, tid);

    const uint4* Hi4 = (const uint4*)(Ahi + (size_t)blockIdx.x * 16384);
    const uint4* Lo4 = (const uint4*)(Alo + (size_t)blockIdx.x * 16384);
    float* sscale = (float*)(smem + SO_SCALE);
    float* sshift = (float*)(smem + SO_SHIFT);

    float acc[2][8][4];
    #pragma unroll
    for (int mt = 0; mt < 2; mt++)
        #pragma unroll
        for (int nt = 0; nt < 8; nt++)
            #pragma unroll
            for (int j = 0; j < 4; j++) acc[mt][nt][j] = 0.f;

    #pragma unroll
    for (int kh = 0; kh < 2; kh++) {
        if (mode == 0) load_a_half_copy(smem, Hi4, Lo4, kh, tid);
        else           load_a_half_bn(smem, Hi4, Lo4, kh, tid, sscale, sshift);
        __syncthreads();
        mma_half(acc, sb, kh, wm, wn, lane);
        __syncthreads();
    }

    // Y fragments -> bf16 hi/lo planes in smem (overwrite W1); zero cnt region
    {
        const int cbase = wn * 64 + (lane & 3) * 2;
        const int rbase = wm * 32 + (lane >> 2);
        #pragma unroll
        for (int mt = 0; mt < 2; mt++) {
            int r0 = rbase + mt * 16, r1 = r0 + 8;
            #pragma unroll
            for (int nt = 0; nt < 8; nt++) {
                int c = cbase + nt * 8;
                float y0 = acc[mt][nt][0], y1 = acc[mt][nt][1];
                float y2 = acc[mt][nt][2], y3 = acc[mt][nt][3];
                __nv_bfloat16 h0 = __float2bfloat16(y0), h1 = __float2bfloat16(y1);
                __nv_bfloat16 h2 = __float2bfloat16(y2), h3 = __float2bfloat16(y3);
                *(uint32_t*)(smem + SB_HI + (uint32_t)r0 * SK_BYTES + (uint32_t)c * 2) = pack2(h0, h1);
                *(uint32_t*)(smem + SB_HI + (uint32_t)r1 * SK_BYTES + (uint32_t)c * 2) = pack2(h2, h3);
                *(uint32_t*)(smem + SB_LO + (uint32_t)r0 * SK_BYTES + (uint32_t)c * 2) =
                    pack2(__float2bfloat16(y0 - __bfloat162float(h0)),
                          __float2bfloat16(y1 - __bfloat162float(h1)));
                *(uint32_t*)(smem + SB_LO + (uint32_t)r1 * SK_BYTES + (uint32_t)c * 2) =
                    pack2(__float2bfloat16(y2 - __bfloat162float(h2)),
                          __float2bfloat16(y3 - __bfloat162float(h3)));
            }
        }
        uint4* az = (uint4*)(smem + SA_HI);
        for (int i = tid; i < 2176; i += 256) az[i] = make_uint4(0, 0, 0, 0);
    }
    __syncthreads();

    // packed 16-bit pair counts via int atomics
    {
        int* cntw = (int*)(smem + SA_HI);
        const int gb = 1 << layer, npg = NPG0 >> layer;
        const int g0 = blockIdx.x * gb;
        const int tot = gb * EPG;
        for (int idx = tid; idx < tot; idx += 256) {
            int j = idx >> 11;
            int e = (g0 + j) * EPG + (idx & 2047);
            int nb = (g0 + j) * NPG0;
            int d = (dst[e] - nb) >> layer;
            int s = (src[e] - nb) >> layer;
            int row = j * npg + d, col = j * npg + s;
            atomicAdd(&cntw[row * 68 + (col >> 1)], 1 << ((col & 1) * 16));
        }
    }
    __syncthreads();

    // counts -> bf16 Abar (+I), in place
    {
        uint32_t* cw = (uint32_t*)(smem + SA_HI);
        for (int i = tid; i < 128 * 64; i += 256) {
            int row = i >> 6, w = i & 63;
            int col = w * 2;
            uint32_t v = cw[row * 68 + w];
            float v0 = (float)(v & 0xFFFFu) + ((row == col)     ? 1.f : 0.f);
            float v1 = (float)(v >> 16)     + ((row == col + 1) ? 1.f : 0.f);
            cw[row * 68 + w] = pack2(__float2bfloat16(v0), __float2bfloat16(v1));
        }
    }
    __syncthreads();

    // agg MMA: acc2 = Abar @ (Yhi + Ylo)
    float acc2[2][8][4];
    #pragma unroll
    for (int mt = 0; mt < 2; mt++)
        #pragma unroll
        for (int nt = 0; nt < 8; nt++)
            #pragma unroll
            for (int j = 0; j < 4; j++) acc2[mt][nt][j] = 0.f;
    {
        const uint32_t aA = sb + SA_HI + (uint32_t)(wm * 32 + (lane & 15)) * SK_BYTES
                          + (uint32_t)(lane >> 4) * 16;
        const uint32_t aB = sb + SB_HI + (uint32_t)(lane & 15) * SK_BYTES
                          + (uint32_t)(wn * 128) + (uint32_t)(lane >> 4) * 16;
        #pragma unroll
        for (int ks = 0; ks < 8; ks++) {
            uint32_t a[2][4], bh[4][4], bl[4][4];
            #pragma unroll
            for (int mt = 0; mt < 2; mt++)
                LDSM_X4(a[mt], aA + (uint32_t)mt * (16 * SK_BYTES) + (uint32_t)ks * 32);
            #pragma unroll
            for (int nt2 = 0; nt2 < 4; nt2++) {
                uint32_t bd = aB + (uint32_t)ks * (16 * SK_BYTES) + (uint32_t)nt2 * 32;
                LDSM_X4T(bh[nt2], bd);
                LDSM_X4T(bl[nt2], bd + (SB_LO - SB_HI));
            }
            #pragma unroll
            for (int mt = 0; mt < 2; mt++)
                #pragma unroll
                for (int nt = 0; nt < 8; nt++) {
                    uint32_t b0h = bh[nt >> 1][(nt & 1) * 2], b1h = bh[nt >> 1][(nt & 1) * 2 + 1];
                    uint32_t b0l = bl[nt >> 1][(nt & 1) * 2], b1l = bl[nt >> 1][(nt & 1) * 2 + 1];
                    MMA_BF16(acc2[mt][nt], a[mt], b0h, b1h);
                    MMA_BF16(acc2[mt][nt], a[mt], b0l, b1l);
                }
        }
    }
    epilogue_planes(acc2, (float*)(smem + SO_BIAS),
                    Ohi + (size_t)blockIdx.x * 16384, Olo + (size_t)blockIdx.x * 16384,
                    statsOut, wm, wn, lane);
}

// ---------------- pool: planes in -> planes out + embd sums/stats --------------
__global__ __launch_bounds__(256) void pool_kernel(
    const __nv_bfloat16* __restrict__ Ghi, const __nv_bfloat16* __restrict__ Glo,
    const float* __restrict__ bnG, const float* __restrict__ bnB,
    const float* __restrict__ statsIn, float nIn,
    __nv_bfloat16* __restrict__ Xhi, __nv_bfloat16* __restrict__ Xlo,
    float* __restrict__ embraw, float* __restrict__ statsOut, int npg_in) {
    __shared__ float es[128], psc[128], psh[128];
    const int g = blockIdx.x, tid = threadIdx.x;
    if (tid < 128) {
        es[tid] = 0.f;
        float sv = statsIn[tid], qv = statsIn[128 + tid];
        float m = sv / nIn, v = qv / nIn - m * m;
        float c_ = bnG[tid] * rsqrtf(v + BN_EPS);
        psc[tid] = c_;
        psh[tid] = fmaf(-m, c_, bnB[tid]);
    }
    __syncthreads();

    const int npg_out = npg_in >> 1;
    const uint4* gh = (const uint4*)(Ghi + (size_t)g * npg_in * 128);
    const uint4* gl = (const uint4*)(Glo + (size_t)g * npg_in * 128);
    uint4* xh = (uint4*)(Xhi + (size_t)g * npg_out * 128);
    uint4* xl = (uint4*)(Xlo + (size_t)g * npg_out * 128);

    for (int i = tid; i < npg_out * 16; i += 256) {    // groups of 8 cols
        int row = i >> 4, gk = i & 15;
        int c0 = gk * 8;
        uint4 h0 = gh[(2 * row) * 16 + gk],     l0 = gl[(2 * row) * 16 + gk];
        uint4 h1 = gh[(2 * row + 1) * 16 + gk], l1 = gl[(2 * row + 1) * 16 + gk];
        uint32_t h0w[4] = {h0.x, h0.y, h0.z, h0.w}, l0w[4] = {l0.x, l0.y, l0.z, l0.w};
        uint32_t h1w[4] = {h1.x, h1.y, h1.z, h1.w}, l1w[4] = {l1.x, l1.y, l1.z, l1.w};
        uint32_t oph[4], opl[4];
        #pragma unroll
        for (int j = 0; j < 4; j++) {
            int c = c0 + 2 * j;
            float a0 = bflo(h0w[j]) + bflo(l0w[j]);
            float a1 = bfhi(h0w[j]) + bfhi(l0w[j]);
            float b0 = bflo(h1w[j]) + bflo(l1w[j]);
            float b1 = bfhi(h1w[j]) + bfhi(l1w[j]);
            float p0 = (fmaxf(fmaf(a0, psc[c],     psh[c]),     0.f)
                      + fmaxf(fmaf(b0, psc[c],     psh[c]),     0.f)) * INV_SQRT2;
            float p1 = (fmaxf(fmaf(a1, psc[c + 1], psh[c + 1]), 0.f)
                      + fmaxf(fmaf(b1, psc[c + 1], psh[c + 1]), 0.f)) * INV_SQRT2;
            __nv_bfloat16 ph0 = __float2bfloat16(p0), ph1 = __float2bfloat16(p1);
            oph[j] = pack2(ph0, ph1);
            opl[j] = pack2(__float2bfloat16(p0 - __bfloat162float(ph0)),
                           __float2bfloat16(p1 - __bfloat162float(ph1)));
            atomicAdd(&es[c],     p0);
            atomicAdd(&es[c + 1], p1);
        }
        xh[i] = make_uint4(oph[0], oph[1], oph[2], oph[3]);
        xl[i] = make_uint4(opl[0], opl[1], opl[2], opl[3]);
    }
    __syncthreads();
    if (tid < 128) {
        float v = es[tid];
        embraw[g * 128 + tid] = v;
        atomicAdd(&statsOut[tid], v);
        atomicAdd(&statsOut[128 + tid], v * v);
    }
}

// ---------------- final linear with inline embedding-BN ------------------------
__global__ void final_linear_kernel(
    const float* __restrict__ embraw, const float* __restrict__ statsAll,
    const float* __restrict__ bneG, const float* __restrict__ bneB,
    const float* __restrict__ W, const float* __restrict__ b, float* __restrict__ out) {
    const int g = blockIdx.x, lane = threadIdx.x;
    float acc[C_CLASSES];
    #pragma unroll
    for (int c = 0; c < C_CLASSES; c++) acc[c] = 0.f;
    for (int k = lane; k < L_LAYERS * H_DIM; k += 32) {
        int layer = k >> 7, c = k & 127;
        const float* st = statsAll + (3 + 3 * layer) * 256;
        float m = st[c] / (float)G_GRAPHS;
        float v = st[128 + c] / (float)G_GRAPHS - m * m;
        float sc = bneG[layer * 128 + c] * rsqrtf(v + BN_EPS);
        float sh = fmaf(-m, sc, bneB[layer * 128 + c]);
        float e = fmaxf(fmaf(embraw[(size_t)layer * G_GRAPHS * 128 + g * 128 + c], sc, sh), 0.f);
        #pragma unroll
        for (int c10 = 0; c10 < C_CLASSES; c10++)
            acc[c10] = fmaf(e, W[k * C_CLASSES + c10], acc[c10]);
    }
    #pragma unroll
    for (int off = 16; off > 0; off >>= 1)
        #pragma unroll
        for (int c = 0; c < C_CLASSES; c++)
            acc[c] += __shfl_down_sync(0xFFFFFFFFu, acc[c], off);
    if (lane == 0) {
        #pragma unroll
        for (int c = 0; c < C_CLASSES; c++)
            out[g * C_CLASSES + c] = acc[c] + b[c];
    }
}

// ---------------- host orchestration ----------------
extern "C" void kernel_launch(void* const* d_in, const int* in_sizes, int n_in,
                              void* d_out, int out_size) {
    const float* x           = (const float*)d_in[0];
    const int*   ei          = (const int*)d_in[1];
    const int*   src         = ei;
    const int*   dst         = ei + E_EDGES;
    const float* lin_start_w = (const float*)d_in[2];
    const float* lin_start_b = (const float*)d_in[3];
    const float* bn_start_g  = (const float*)d_in[4];
    const float* bn_start_b  = (const float*)d_in[5];
    const float* conv_w1     = (const float*)d_in[6];
    const float* conv_b1     = (const float*)d_in[7];
    const float* conv_bn_g   = (const float*)d_in[8];
    const float* conv_bn_b   = (const float*)d_in[9];
    const float* conv_w2     = (const float*)d_in[10];
    const float* conv_b2     = (const float*)d_in[11];
    const float* bn_g        = (const float*)d_in[12];
    const float* bn_b        = (const float*)d_in[13];
    const float* bne_g       = (const float*)d_in[14];
    const float* bne_b       = (const float*)d_in[15];
    const float* lin_w       = (const float*)d_in[16];
    const float* lin_b       = (const float*)d_in[17];
    float* out = (float*)d_out;

    float *bufA, *bufB, *bufX, *embraw, *statsAll;
    __nv_bfloat16* wimg;
    cudaGetSymbolAddress((void**)&bufA,     g_bufA);
    cudaGetSymbolAddress((void**)&bufB,     g_bufB);
    cudaGetSymbolAddress((void**)&bufX,     g_X);
    cudaGetSymbolAddress((void**)&embraw,   g_embraw);
    cudaGetSymbolAddress((void**)&statsAll, g_statsAll);
    cudaGetSymbolAddress((void**)&wimg,     g_wimg);

    __nv_bfloat16* Ahi = (__nv_bfloat16*)bufA;  __nv_bfloat16* Alo = Ahi + PLANE_AB;
    __nv_bfloat16* Bhi = (__nv_bfloat16*)bufB;  __nv_bfloat16* Blo = Bhi + PLANE_AB;
    __nv_bfloat16* Xhi = (__nv_bfloat16*)bufX;  __nv_bfloat16* Xlo = Xhi + PLANE_X;

    cudaFuncSetAttribute(tc_gemm, cudaFuncAttributeMaxDynamicSharedMemorySize, BIG_SMEM);
    cudaFuncSetAttribute(fused_layer, cudaFuncAttributeMaxDynamicSharedMemorySize, BIG_SMEM);

    transw_kernel<<<8, 256>>>(lin_start_w, conv_w1, conv_w2, wimg, statsAll);

    float* slot0 = statsAll;

    // Stage 0: Y0 planes (bufB) = x @ W_start + b  (stats slot0)
    tc_gemm<<<N_NODES / 128, 256, BIG_SMEM>>>(
        x, nullptr, nullptr, wimg, lin_start_b,
        nullptr, nullptr, nullptr, 0.f, 0, 0, Bhi, Blo, slot0);

    for (int i = 0; i < L_LAYERS; i++) {
        const int n = N_NODES >> i;
        const int npg = NPG0 >> i;
        float* slotH = statsAll + (1 + 3 * i) * 256;
        float* slotG = statsAll + (2 + 3 * i) * 256;
        float* slotE = statsAll + (3 + 3 * i) * 256;

        // fused: H planes (bufA) = (I+A)(op(in)@W1) + b1
        // layer0: in = Y0 planes (bufB), op = BN(slot0)+relu; layers>=1: in = X planes
        const __nv_bfloat16* inHi = (i == 0) ? Bhi : Xhi;
        const __nv_bfloat16* inLo = (i == 0) ? Blo : Xlo;
        fused_layer<<<n / 128, 256, BIG_SMEM>>>(
            inHi, inLo, wimg + (size_t)(1 + i) * 32768, src, dst, conv_b1 + i * H_DIM,
            (i == 0) ? bn_start_g : nullptr, (i == 0) ? bn_start_b : nullptr,
            (i == 0) ? slot0 : nullptr, (float)N_NODES, (i == 0) ? 1 : 0,
            Ahi, Alo, slotH, i);

        // G planes (bufB) = relu(bn(H)) @ W2 + b2  (stats slotG)
        tc_gemm<<<n / 128, 256, BIG_SMEM>>>(
            nullptr, Ahi, Alo, wimg + (size_t)(4 + i) * 32768, conv_b2 + i * H_DIM,
            conv_bn_g + i * H_DIM, conv_bn_b + i * H_DIM, slotH, (float)n, 1, 1,
            Bhi, Blo, slotG);

        // pool: bn(G)+relu -> Haar -> X planes; embd sums + stats slotE
        pool_kernel<<<G_GRAPHS, 256>>>(
            Bhi, Blo, bn_g + i * H_DIM, bn_b + i * H_DIM, slotG, (float)n,
            Xhi, Xlo, embraw + (size_t)i * G_GRAPHS * H_DIM, slotE, npg);
    }

    final_linear_kernel<<<G_GRAPHS, 32>>>(
        embraw, statsAll, bne_g, bne_b, lin_w, lin_b, out);
}

// round 10
// speedup vs baseline: 1.0560x; 1.0560x over previous
#include <cuda_runtime.h>
#include <cuda_bf16.h>
#include <math.h>
#include <stdint.h>

// ---------------- problem constants ----------------
#define N_NODES   131072
#define G_GRAPHS  1024
#define NPG0      128
#define H_DIM     128
#define E_EDGES   2097152
#define EPG       2048
#define L_LAYERS  3
#define C_CLASSES 10
#define BN_EPS    1e-5f
#define INV_SQRT2 0.70710678118654752440f
#define N_SLOTS   10

// ---------------- scratch ----------------
__device__ float g_bufA[(size_t)N_NODES * H_DIM];
__device__ float g_bufB[(size_t)N_NODES * H_DIM];
__device__ float g_X[(size_t)(N_NODES / 2) * H_DIM];
__device__ float g_embraw[L_LAYERS * G_GRAPHS * H_DIM];
__device__ float g_statsAll[N_SLOTS * 256];
__device__ __nv_bfloat16 g_wimg[7 * 2 * 16384];   // [7 weights][hi|lo][K=128][N=128]

// ---------------- helpers ----------------
__device__ __forceinline__ uint32_t smem_u32(const void* p) {
    uint32_t a;
    asm("{ .reg .u64 t; cvta.to.shared.u64 t, %1; cvt.u32.u64 %0, t; }" : "=r"(a) : "l"(p));
    return a;
}
__device__ __forceinline__ uint32_t pack2(__nv_bfloat16 a, __nv_bfloat16 b) {
    __nv_bfloat162 t; t.x = a; t.y = b; return *(uint32_t*)&t;
}
#define LDSM_X4(r, a) \
    asm volatile("ldmatrix.sync.aligned.m8n8.x4.shared.b16 {%0,%1,%2,%3}, [%4];" \
        : "=r"((r)[0]), "=r"((r)[1]), "=r"((r)[2]), "=r"((r)[3]) : "r"(a))
#define LDSM_X4T(r, a) \
    asm volatile("ldmatrix.sync.aligned.m8n8.x4.trans.shared.b16 {%0,%1,%2,%3}, [%4];" \
        : "=r"((r)[0]), "=r"((r)[1]), "=r"((r)[2]), "=r"((r)[3]) : "r"(a))
#define MMA_BF16(d, a, b0, b1) \
    asm volatile("mma.sync.aligned.m16n8k16.row.col.f32.bf16.bf16.f32 " \
        "{%0,%1,%2,%3}, {%4,%5,%6,%7}, {%8,%9}, {%0,%1,%2,%3};" \
        : "+f"((d)[0]), "+f"((d)[1]), "+f"((d)[2]), "+f"((d)[3]) \
        : "r"((a)[0]), "r"((a)[1]), "r"((a)[2]), "r"((a)[3]), "r"(b0), "r"(b1))

#define SK_BYTES  272   // full-K bf16 row stride (B planes / Abar)
#define AQ_BYTES  48    // 16-col chunk row stride (32B data + 16B pad; conflict-free LDSM)
#define AQ_PLANE  6144  // 128 * 48
#define AQ_BUF    12288 // hi + lo

// ---- shared smem layout (both big kernels) ----
#define SB_HI     0
#define SB_LO     34816
#define SA_BASE   69632              // chunk buf0 @0, buf1 @+12288; fused: cnt/Abar (34816)
#define SO_BIAS   104448
#define SO_SCALE  104960
#define SO_SHIFT  105472
#define BIG_SMEM  105984

// ---------------- weight bf16 split + stats zero ----------------
__global__ void transw_kernel(const float* __restrict__ w0, const float* __restrict__ w1,
                              const float* __restrict__ w2, __nv_bfloat16* __restrict__ img,
                              float* __restrict__ statsAll) {
    int b = blockIdx.x;
    if (b == 7) {
        for (int i = threadIdx.x; i < N_SLOTS * 256; i += blockDim.x) statsAll[i] = 0.f;
        return;
    }
    const float* W = (b == 0) ? w0 : ((b <= 3) ? w1 + (size_t)(b - 1) * 16384
                                               : w2 + (size_t)(b - 4) * 16384);
    __nv_bfloat16* hi = img + (size_t)b * 32768;
    __nv_bfloat16* lo = hi + 16384;
    for (int i = threadIdx.x; i < 16384; i += blockDim.x) {
        float v = W[i];
        __nv_bfloat16 h = __float2bfloat16(v);
        hi[i] = h;
        lo[i] = __float2bfloat16(v - __bfloat162float(h));
    }
}

// ---------------- chunked A pipeline pieces ----------------
// chunk c covers cols [c*16, c*16+16). Each thread owns 8 floats (row, 8-col group).
__device__ __forceinline__ void ldg_chunk(float4& u, float4& v,
                                          const float4* A4, int c, int tid) {
    int row = tid >> 1, g = tid & 1;
    u = A4[row * 32 + c * 4 + g * 2];
    v = A4[row * 32 + c * 4 + g * 2 + 1];
}
__device__ __forceinline__ void sts_chunk(const float4& u, const float4& v,
                                          char* smem, uint32_t bufoff, int c, int tid,
                                          int mode, const float* sscale, const float* sshift) {
    int row = tid >> 1, g = tid & 1;
    float xv[8] = {u.x, u.y, u.z, u.w, v.x, v.y, v.z, v.w};
    if (mode) {
        int c0 = c * 16 + g * 8;
        #pragma unroll
        for (int j = 0; j < 8; j++)
            xv[j] = fmaxf(fmaf(xv[j], sscale[c0 + j], sshift[c0 + j]), 0.f);
    }
    uint32_t hp[4], lp[4];
    #pragma unroll
    for (int j = 0; j < 4; j++) {
        __nv_bfloat16 h0 = __float2bfloat16(xv[2 * j]);
        __nv_bfloat16 h1 = __float2bfloat16(xv[2 * j + 1]);
        hp[j] = pack2(h0, h1);
        lp[j] = pack2(__float2bfloat16(xv[2 * j]     - __bfloat162float(h0)),
                      __float2bfloat16(xv[2 * j + 1] - __bfloat162float(h1)));
    }
    // FIX (R9 bug): chunk buffers live at SA_BASE, not smem base.
    uint32_t off = SA_BASE + bufoff + (uint32_t)row * AQ_BYTES + (uint32_t)g * 16;
    *(uint4*)(smem + off)            = make_uint4(hp[0], hp[1], hp[2], hp[3]);
    *(uint4*)(smem + off + AQ_PLANE) = make_uint4(lp[0], lp[1], lp[2], lp[3]);
}

// 3-term MMA for one k16 chunk (A from chunk buffer, B from full planes at kidx=c)
__device__ __forceinline__ void mma_chunk(
    float acc[2][8][4], uint32_t sb, uint32_t aqoff, int c, int wm, int wn, int lane) {
    const uint32_t aA = sb + SA_BASE + aqoff
                      + (uint32_t)(wm * 32 + (lane & 15)) * AQ_BYTES
                      + (uint32_t)(lane >> 4) * 16;
    const uint32_t aB = sb + SB_HI + (uint32_t)(lane & 15) * SK_BYTES
                      + (uint32_t)(wn * 128) + (uint32_t)(lane >> 4) * 16;
    uint32_t ah[2][4], al[2][4], bh[4][4], bl[4][4];
    #pragma unroll
    for (int mt = 0; mt < 2; mt++) {
        uint32_t ad = aA + (uint32_t)mt * (16 * AQ_BYTES);
        LDSM_X4(ah[mt], ad);
        LDSM_X4(al[mt], ad + AQ_PLANE);
    }
    #pragma unroll
    for (int nt2 = 0; nt2 < 4; nt2++) {
        uint32_t bd = aB + (uint32_t)c * (16 * SK_BYTES) + (uint32_t)nt2 * 32;
        LDSM_X4T(bh[nt2], bd);
        LDSM_X4T(bl[nt2], bd + (SB_LO - SB_HI));
    }
    #pragma unroll
    for (int mt = 0; mt < 2; mt++)
        #pragma unroll
        for (int nt = 0; nt < 8; nt++) {
            uint32_t b0h = bh[nt >> 1][(nt & 1) * 2], b1h = bh[nt >> 1][(nt & 1) * 2 + 1];
            uint32_t b0l = bl[nt >> 1][(nt & 1) * 2], b1l = bl[nt >> 1][(nt & 1) * 2 + 1];
            MMA_BF16(acc[mt][nt], ah[mt], b0h, b1h);
            MMA_BF16(acc[mt][nt], ah[mt], b0l, b1l);
            MMA_BF16(acc[mt][nt], al[mt], b0h, b1h);
        }
}

// pipelined GEMM mainloop: acc += op(A) @ W  (A fp32 global, W planes in smem)
__device__ __forceinline__ void gemm_mainloop(
    float acc[2][8][4], char* smem, uint32_t sb, const float4* A4,
    int tid, int wm, int wn, int lane, int mode,
    const float* sscale, const float* sshift) {
    float4 u, v;
    ldg_chunk(u, v, A4, 0, tid);
    sts_chunk(u, v, smem, 0, 0, tid, mode, sscale, sshift);
    __syncthreads();
    #pragma unroll
    for (int c = 0; c < 8; c++) {
        if (c < 7) ldg_chunk(u, v, A4, c + 1, tid);        // in flight during MMA
        mma_chunk(acc, sb, (uint32_t)(c & 1) * AQ_BUF, c, wm, wn, lane);
        if (c < 7) sts_chunk(u, v, smem, (uint32_t)((c + 1) & 1) * AQ_BUF, c + 1,
                             tid, mode, sscale, sshift);
        __syncthreads();
    }
}

// epilogue: + bias, channel stats, fp32 store
__device__ __forceinline__ void epilogue_f32(
    float acc[2][8][4], const float* sbias, float* Cb, float* statsOut,
    int wm, int wn, int lane) {
    float s[8][2], q[8][2];
    #pragma unroll
    for (int nt = 0; nt < 8; nt++) { s[nt][0] = s[nt][1] = q[nt][0] = q[nt][1] = 0.f; }
    const int cbase = wn * 64 + (lane & 3) * 2;
    const int rbase = wm * 32 + (lane >> 2);
    #pragma unroll
    for (int mt = 0; mt < 2; mt++) {
        int r0 = rbase + mt * 16, r1 = r0 + 8;
        #pragma unroll
        for (int nt = 0; nt < 8; nt++) {
            int c = cbase + nt * 8;
            float b0 = sbias[c], b1 = sbias[c + 1];
            float y0 = acc[mt][nt][0] + b0, y1 = acc[mt][nt][1] + b1;
            float y2 = acc[mt][nt][2] + b0, y3 = acc[mt][nt][3] + b1;
            s[nt][0] += y0 + y2;           s[nt][1] += y1 + y3;
            q[nt][0] += y0 * y0 + y2 * y2; q[nt][1] += y1 * y1 + y3 * y3;
            *(float2*)(Cb + r0 * 128 + c) = make_float2(y0, y1);
            *(float2*)(Cb + r1 * 128 + c) = make_float2(y2, y3);
        }
    }
    #pragma unroll
    for (int off = 16; off >= 4; off >>= 1)
        #pragma unroll
        for (int nt = 0; nt < 8; nt++) {
            s[nt][0] += __shfl_down_sync(0xFFFFFFFFu, s[nt][0], off);
            s[nt][1] += __shfl_down_sync(0xFFFFFFFFu, s[nt][1], off);
            q[nt][0] += __shfl_down_sync(0xFFFFFFFFu, q[nt][0], off);
            q[nt][1] += __shfl_down_sync(0xFFFFFFFFu, q[nt][1], off);
        }
    if (lane < 4) {
        #pragma unroll
        for (int nt = 0; nt < 8; nt++) {
            int c = cbase + nt * 8;
            atomicAdd(&statsOut[c],           s[nt][0]);
            atomicAdd(&statsOut[c + 1],       s[nt][1]);
            atomicAdd(&statsOut[128 + c],     q[nt][0]);
            atomicAdd(&statsOut[128 + c + 1], q[nt][1]);
        }
    }
}

// BN coef setup into smem (threads 0..127), then sync
__device__ __forceinline__ void setup_coefs(
    char* smem, const float* bias, const float* bnG, const float* bnB,
    const float* statsIn, float nIn, int mode, int tid) {
    float* sbias  = (float*)(smem + SO_BIAS);
    float* sscale = (float*)(smem + SO_SCALE);
    float* sshift = (float*)(smem + SO_SHIFT);
    if (tid < 128) {
        sbias[tid] = bias[tid];
        if (mode) {
            float s = statsIn[tid], q = statsIn[128 + tid];
            float m = s / nIn, v = q / nIn - m * m;
            float sc = bnG[tid] * rsqrtf(v + BN_EPS);
            sscale[tid] = sc;
            sshift[tid] = fmaf(-m, sc, bnB[tid]);
        }
    }
    __syncthreads();
}

// copy full B planes (weights) into smem
__device__ __forceinline__ void load_b_planes(char* smem, const __nv_bfloat16* Wimg, int tid) {
    const uint4* bh = (const uint4*)Wimg;
    #pragma unroll
    for (int it = 0; it < 8; it++) {
        int i = tid + it * 256;
        int k = i >> 4, g = i & 15;
        uint32_t off = (uint32_t)k * SK_BYTES + (uint32_t)g * 16;
        *(uint4*)(smem + SB_HI + off) = bh[i];
        *(uint4*)(smem + SB_LO + off) = bh[2048 + i];
    }
}

// ---------------- tc_gemm: C = op(A) @ W + bias, + stats ----------------
__global__ __launch_bounds__(256, 2) void tc_gemm(
    const float* __restrict__ A, const __nv_bfloat16* __restrict__ Wimg,
    const float* __restrict__ bias,
    const float* __restrict__ bnG, const float* __restrict__ bnB,
    const float* __restrict__ statsIn, float nIn, int mode,
    float* __restrict__ Cf, float* __restrict__ statsOut) {
    extern __shared__ char smem[];
    const uint32_t sb = smem_u32(smem);
    const int tid = threadIdx.x, wid = tid >> 5, lane = tid & 31;
    const int wm = wid >> 1, wn = wid & 1;

    setup_coefs(smem, bias, bnG, bnB, statsIn, nIn, mode, tid);
    load_b_planes(smem, Wimg, tid);

    const float4* A4 = (const float4*)(A + (size_t)blockIdx.x * 16384);
    float* sscale = (float*)(smem + SO_SCALE);
    float* sshift = (float*)(smem + SO_SHIFT);

    float acc[2][8][4];
    #pragma unroll
    for (int mt = 0; mt < 2; mt++)
        #pragma unroll
        for (int nt = 0; nt < 8; nt++)
            #pragma unroll
            for (int j = 0; j < 4; j++) acc[mt][nt][j] = 0.f;

    gemm_mainloop(acc, smem, sb, A4, tid, wm, wn, lane, mode, sscale, sshift);

    epilogue_f32(acc, (float*)(smem + SO_BIAS),
                 Cf + (size_t)blockIdx.x * 16384, statsOut, wm, wn, lane);
}

// ---------------- fused layer: H = (I+A)(op(x)@W1) + b1, + stats ----------------
__global__ __launch_bounds__(256, 2) void fused_layer(
    const float* __restrict__ A, const __nv_bfloat16* __restrict__ W1img,
    const int* __restrict__ src, const int* __restrict__ dst,
    const float* __restrict__ bias,
    const float* __restrict__ bnG, const float* __restrict__ bnB,
    const float* __restrict__ statsIn, float nIn, int mode,
    float* __restrict__ H, float* __restrict__ statsOut, int layer) {
    extern __shared__ char smem[];
    const uint32_t sb = smem_u32(smem);
    const int tid = threadIdx.x, wid = tid >> 5, lane = tid & 31;
    const int wm = wid >> 1, wn = wid & 1;

    setup_coefs(smem, bias, bnG, bnB, statsIn, nIn, mode, tid);
    load_b_planes(smem, W1img, tid);

    const float4* A4 = (const float4*)(A + (size_t)blockIdx.x * 16384);
    float* sscale = (float*)(smem + SO_SCALE);
    float* sshift = (float*)(smem + SO_SHIFT);

    float acc[2][8][4];
    #pragma unroll
    for (int mt = 0; mt < 2; mt++)
        #pragma unroll
        for (int nt = 0; nt < 8; nt++)
            #pragma unroll
            for (int j = 0; j < 4; j++) acc[mt][nt][j] = 0.f;

    gemm_mainloop(acc, smem, sb, A4, tid, wm, wn, lane, mode, sscale, sshift);
    __syncthreads();   // everyone done with W1 planes + chunk bufs

    // Y fragments -> bf16 hi/lo planes in smem (overwrite W1 planes); zero cnt region
    {
        const int cbase = wn * 64 + (lane & 3) * 2;
        const int rbase = wm * 32 + (lane >> 2);
        #pragma unroll
        for (int mt = 0; mt < 2; mt++) {
            int r0 = rbase + mt * 16, r1 = r0 + 8;
            #pragma unroll
            for (int nt = 0; nt < 8; nt++) {
                int c = cbase + nt * 8;
                float y0 = acc[mt][nt][0], y1 = acc[mt][nt][1];
                float y2 = acc[mt][nt][2], y3 = acc[mt][nt][3];
                __nv_bfloat16 h0 = __float2bfloat16(y0), h1 = __float2bfloat16(y1);
                __nv_bfloat16 h2 = __float2bfloat16(y2), h3 = __float2bfloat16(y3);
                *(uint32_t*)(smem + SB_HI + (uint32_t)r0 * SK_BYTES + (uint32_t)c * 2) = pack2(h0, h1);
                *(uint32_t*)(smem + SB_HI + (uint32_t)r1 * SK_BYTES + (uint32_t)c * 2) = pack2(h2, h3);
                *(uint32_t*)(smem + SB_LO + (uint32_t)r0 * SK_BYTES + (uint32_t)c * 2) =
                    pack2(__float2bfloat16(y0 - __bfloat162float(h0)),
                          __float2bfloat16(y1 - __bfloat162float(h1)));
                *(uint32_t*)(smem + SB_LO + (uint32_t)r1 * SK_BYTES + (uint32_t)c * 2) =
                    pack2(__float2bfloat16(y2 - __bfloat162float(h2)),
                          __float2bfloat16(y3 - __bfloat162float(h3)));
            }
        }
        uint4* az = (uint4*)(smem + SA_BASE);
        for (int i = tid; i < 2176; i += 256) az[i] = make_uint4(0, 0, 0, 0);
    }
    __syncthreads();

    // packed 16-bit pair counts via int atomics (rows of 68 words = 272 B)
    {
        int* cntw = (int*)(smem + SA_BASE);
        const int gb = 1 << layer, npg = NPG0 >> layer;
        const int g0 = blockIdx.x * gb;
        const int tot = gb * EPG;
        for (int idx = tid; idx < tot; idx += 256) {
            int j = idx >> 11;
            int e = (g0 + j) * EPG + (idx & 2047);
            int nb = (g0 + j) * NPG0;
            int d = (dst[e] - nb) >> layer;
            int s = (src[e] - nb) >> layer;
            int row = j * npg + d, col = j * npg + s;
            atomicAdd(&cntw[row * 68 + (col >> 1)], 1 << ((col & 1) * 16));
        }
    }
    __syncthreads();

    // counts -> bf16 Abar (+I), in place
    {
        uint32_t* cw = (uint32_t*)(smem + SA_BASE);
        for (int i = tid; i < 128 * 64; i += 256) {
            int row = i >> 6, w = i & 63;
            int col = w * 2;
            uint32_t v = cw[row * 68 + w];
            float v0 = (float)(v & 0xFFFFu) + ((row == col)     ? 1.f : 0.f);
            float v1 = (float)(v >> 16)     + ((row == col + 1) ? 1.f : 0.f);
            cw[row * 68 + w] = pack2(__float2bfloat16(v0), __float2bfloat16(v1));
        }
    }
    __syncthreads();

    // agg MMA: acc2 = Abar @ (Yhi + Ylo)
    float acc2[2][8][4];
    #pragma unroll
    for (int mt = 0; mt < 2; mt++)
        #pragma unroll
        for (int nt = 0; nt < 8; nt++)
            #pragma unroll
            for (int j = 0; j < 4; j++) acc2[mt][nt][j] = 0.f;
    {
        const uint32_t aA = sb + SA_BASE + (uint32_t)(wm * 32 + (lane & 15)) * SK_BYTES
                          + (uint32_t)(lane >> 4) * 16;
        const uint32_t aB = sb + SB_HI + (uint32_t)(lane & 15) * SK_BYTES
                          + (uint32_t)(wn * 128) + (uint32_t)(lane >> 4) * 16;
        #pragma unroll
        for (int ks = 0; ks < 8; ks++) {
            uint32_t a[2][4], bh[4][4], bl[4][4];
            #pragma unroll
            for (int mt = 0; mt < 2; mt++)
                LDSM_X4(a[mt], aA + (uint32_t)mt * (16 * SK_BYTES) + (uint32_t)ks * 32);
            #pragma unroll
            for (int nt2 = 0; nt2 < 4; nt2++) {
                uint32_t bd = aB + (uint32_t)ks * (16 * SK_BYTES) + (uint32_t)nt2 * 32;
                LDSM_X4T(bh[nt2], bd);
                LDSM_X4T(bl[nt2], bd + (SB_LO - SB_HI));
            }
            #pragma unroll
            for (int mt = 0; mt < 2; mt++)
                #pragma unroll
                for (int nt = 0; nt < 8; nt++) {
                    uint32_t b0h = bh[nt >> 1][(nt & 1) * 2], b1h = bh[nt >> 1][(nt & 1) * 2 + 1];
                    uint32_t b0l = bl[nt >> 1][(nt & 1) * 2], b1l = bl[nt >> 1][(nt & 1) * 2 + 1];
                    MMA_BF16(acc2[mt][nt], a[mt], b0h, b1h);
                    MMA_BF16(acc2[mt][nt], a[mt], b0l, b1l);
                }
        }
    }
    epilogue_f32(acc2, (float*)(smem + SO_BIAS),
                 H + (size_t)blockIdx.x * 16384, statsOut, wm, wn, lane);
}

// ---------------- pool: inline BN+relu -> Haar -> graph sum + embd stats -------
__global__ __launch_bounds__(256) void pool_kernel(
    const float* __restrict__ Hin,
    const float* __restrict__ bnG, const float* __restrict__ bnB,
    const float* __restrict__ statsIn, float nIn,
    float* __restrict__ Xout, float* __restrict__ embraw,
    float* __restrict__ statsOut, int npg_in) {
    __shared__ float es[128], psc[128], psh[128];
    const int g = blockIdx.x, tid = threadIdx.x;
    if (tid < 128) {
        es[tid] = 0.f;
        float sv = statsIn[tid], qv = statsIn[128 + tid];
        float m = sv / nIn, v = qv / nIn - m * m;
        float c_ = bnG[tid] * rsqrtf(v + BN_EPS);
        psc[tid] = c_;
        psh[tid] = fmaf(-m, c_, bnB[tid]);
    }
    __syncthreads();

    const int npg_out = npg_in >> 1;
    const float4* in4 = (const float4*)(Hin + (size_t)g * npg_in * 128);
    float4* out4 = (float4*)(Xout + (size_t)g * npg_out * 128);

    for (int i = tid; i < npg_out * 32; i += 256) {
        int row = i >> 5, c4 = i & 31, c = c4 * 4;
        float4 a = in4[(2 * row) * 32 + c4];
        float4 b = in4[(2 * row + 1) * 32 + c4];
        float4 p;
        p.x = (fmaxf(fmaf(a.x, psc[c+0], psh[c+0]), 0.f) + fmaxf(fmaf(b.x, psc[c+0], psh[c+0]), 0.f)) * INV_SQRT2;
        p.y = (fmaxf(fmaf(a.y, psc[c+1], psh[c+1]), 0.f) + fmaxf(fmaf(b.y, psc[c+1], psh[c+1]), 0.f)) * INV_SQRT2;
        p.z = (fmaxf(fmaf(a.z, psc[c+2], psh[c+2]), 0.f) + fmaxf(fmaf(b.z, psc[c+2], psh[c+2]), 0.f)) * INV_SQRT2;
        p.w = (fmaxf(fmaf(a.w, psc[c+3], psh[c+3]), 0.f) + fmaxf(fmaf(b.w, psc[c+3], psh[c+3]), 0.f)) * INV_SQRT2;
        out4[i] = p;
        atomicAdd(&es[c + 0], p.x);
        atomicAdd(&es[c + 1], p.y);
        atomicAdd(&es[c + 2], p.z);
        atomicAdd(&es[c + 3], p.w);
    }
    __syncthreads();
    if (tid < 128) {
        float v = es[tid];
        embraw[g * 128 + tid] = v;
        atomicAdd(&statsOut[tid], v);
        atomicAdd(&statsOut[128 + tid], v * v);
    }
}

// ---------------- final linear with inline embedding-BN ------------------------
__global__ void final_linear_kernel(
    const float* __restrict__ embraw, const float* __restrict__ statsAll,
    const float* __restrict__ bneG, const float* __restrict__ bneB,
    const float* __restrict__ W, const float* __restrict__ b, float* __restrict__ out) {
    const int g = blockIdx.x, lane = threadIdx.x;
    float acc[C_CLASSES];
    #pragma unroll
    for (int c = 0; c < C_CLASSES; c++) acc[c] = 0.f;
    for (int k = lane; k < L_LAYERS * H_DIM; k += 32) {
        int layer = k >> 7, c = k & 127;
        const float* st = statsAll + (3 + 3 * layer) * 256;
        float m = st[c] / (float)G_GRAPHS;
        float v = st[128 + c] / (float)G_GRAPHS - m * m;
        float sc = bneG[layer * 128 + c] * rsqrtf(v + BN_EPS);
        float sh = fmaf(-m, sc, bneB[layer * 128 + c]);
        float e = fmaxf(fmaf(embraw[(size_t)layer * G_GRAPHS * 128 + g * 128 + c], sc, sh), 0.f);
        #pragma unroll
        for (int c10 = 0; c10 < C_CLASSES; c10++)
            acc[c10] = fmaf(e, W[k * C_CLASSES + c10], acc[c10]);
    }
    #pragma unroll
    for (int off = 16; off > 0; off >>= 1)
        #pragma unroll
        for (int c = 0; c < C_CLASSES; c++)
            acc[c] += __shfl_down_sync(0xFFFFFFFFu, acc[c], off);
    if (lane == 0) {
        #pragma unroll
        for (int c = 0; c < C_CLASSES; c++)
            out[g * C_CLASSES + c] = acc[c] + b[c];
    }
}

// ---------------- host orchestration ----------------
extern "C" void kernel_launch(void* const* d_in, const int* in_sizes, int n_in,
                              void* d_out, int out_size) {
    const float* x           = (const float*)d_in[0];
    const int*   ei          = (const int*)d_in[1];
    const int*   src         = ei;
    const int*   dst         = ei + E_EDGES;
    const float* lin_start_w = (const float*)d_in[2];
    const float* lin_start_b = (const float*)d_in[3];
    const float* bn_start_g  = (const float*)d_in[4];
    const float* bn_start_b  = (const float*)d_in[5];
    const float* conv_w1     = (const float*)d_in[6];
    const float* conv_b1     = (const float*)d_in[7];
    const float* conv_bn_g   = (const float*)d_in[8];
    const float* conv_bn_b   = (const float*)d_in[9];
    const float* conv_w2     = (const float*)d_in[10];
    const float* conv_b2     = (const float*)d_in[11];
    const float* bn_g        = (const float*)d_in[12];
    const float* bn_b        = (const float*)d_in[13];
    const float* bne_g       = (const float*)d_in[14];
    const float* bne_b       = (const float*)d_in[15];
    const float* lin_w       = (const float*)d_in[16];
    const float* lin_b       = (const float*)d_in[17];
    float* out = (float*)d_out;

    float *bufA, *bufB, *bufX, *embraw, *statsAll;
    __nv_bfloat16* wimg;
    cudaGetSymbolAddress((void**)&bufA,     g_bufA);
    cudaGetSymbolAddress((void**)&bufB,     g_bufB);
    cudaGetSymbolAddress((void**)&bufX,     g_X);
    cudaGetSymbolAddress((void**)&embraw,   g_embraw);
    cudaGetSymbolAddress((void**)&statsAll, g_statsAll);
    cudaGetSymbolAddress((void**)&wimg,     g_wimg);

    cudaFuncSetAttribute(tc_gemm, cudaFuncAttributeMaxDynamicSharedMemorySize, BIG_SMEM);
    cudaFuncSetAttribute(fused_layer, cudaFuncAttributeMaxDynamicSharedMemorySize, BIG_SMEM);

    transw_kernel<<<8, 256>>>(lin_start_w, conv_w1, conv_w2, wimg, statsAll);

    float* slot0 = statsAll;

    // Stage 0: bufA = x @ W_start + b  (stats slot0)
    tc_gemm<<<N_NODES / 128, 256, BIG_SMEM>>>(
        x, wimg, lin_start_b, nullptr, nullptr, nullptr, 0.f, 0, bufA, slot0);

    for (int i = 0; i < L_LAYERS; i++) {
        const int n = N_NODES >> i;
        const int npg = NPG0 >> i;
        float* slotH = statsAll + (1 + 3 * i) * 256;
        float* slotG = statsAll + (2 + 3 * i) * 256;
        float* slotE = statsAll + (3 + 3 * i) * 256;

        // fused: H = (I+A)(op(x)@W1) + b1   (layer0: op = BN(slot0)+relu, in-place bufA)
        const float* ain = (i == 0) ? (const float*)bufA : (const float*)bufX;
        fused_layer<<<n / 128, 256, BIG_SMEM>>>(
            ain, wimg + (size_t)(1 + i) * 32768, src, dst, conv_b1 + i * H_DIM,
            (i == 0) ? bn_start_g : nullptr, (i == 0) ? bn_start_b : nullptr,
            (i == 0) ? slot0 : nullptr, (float)N_NODES, (i == 0) ? 1 : 0,
            bufA, slotH, i);

        // G = relu(bn(H)) @ W2 + b2   (stats slotG)
        tc_gemm<<<n / 128, 256, BIG_SMEM>>>(
            bufA, wimg + (size_t)(4 + i) * 32768, conv_b2 + i * H_DIM,
            conv_bn_g + i * H_DIM, conv_bn_b + i * H_DIM, slotH, (float)n, 1,
            bufB, slotG);

        // pool: bn(G)+relu -> Haar -> x_{i+1}; embd sums + stats slotE
        pool_kernel<<<G_GRAPHS, 256>>>(
            bufB, bn_g + i * H_DIM, bn_b + i * H_DIM, slotG, (float)n,
            bufX, embraw + (size_t)i * G_GRAPHS * H_DIM, slotE, npg);
    }

    final_linear_kernel<<<G_GRAPHS, 32>>>(
        embraw, statsAll, bne_g, bne_b, lin_w, lin_b, out);
}